// round 2
// baseline (speedup 1.0000x reference)
#include <cuda_runtime.h>
#include <stdint.h>

// Problem constants (fixed by reference setup_inputs)
#define Bv 512
#define Nv 128
#define Dv 256
#define Fv (Nv + 1)          // 129

// Output layout (concatenated flattened reference outputs, float32):
//   h           : Bv*Nv*Dv   = 16,777,216
//   edge_index  : 2*Bv*Nv*Nv = 16,777,216  (row stream, then col stream)
//   edge_weights: Bv*Nv*Nv   =  8,388,608
//   edge_types  : Bv*Nv*Nv   =  8,388,608
#define OFF_H    0
#define OFF_ROW  (Bv*Nv*Dv)                       // 16777216
#define OFF_COL  (OFF_ROW + Bv*Nv*Nv)             // 25165824
#define OFF_W    (OFF_COL + Bv*Nv*Nv)             // 33554432
#define OFF_T    (OFF_W   + Bv*Nv*Nv)             // 41943040
#define TOTAL_OUT (OFF_T + Bv*Nv*Nv)              // 50331648

__device__ __forceinline__ float fast_tanh(float x) {
    float y;
    asm("tanh.approx.f32 %0, %1;" : "=f"(y) : "f"(x));
    return y;
}

// h[b,n,d] = tanh( z[b,n]*W[n,0,d] + W[n,n+1,d] + bias[n,d] )
// (one-hot in feats selects W row n+1; the einsum degenerates to an axpy)
#define B_PER_BLK 32
__global__ void __launch_bounds__(Dv) h_kernel(
    const float* __restrict__ z,
    const float* __restrict__ W,
    const float* __restrict__ bias,
    float* __restrict__ out)
{
    const int n = blockIdx.x;
    const int d = threadIdx.x;

    const float* Wn = W + (size_t)n * (Fv * Dv);
    const float a  = __ldg(Wn + d);                          // W[n,0,d]
    const float c  = __ldg(Wn + (n + 1) * Dv + d)            // W[n,n+1,d]
                   + __ldg(bias + n * Dv + d);               // + b[n,d]

    const int b0 = blockIdx.y * B_PER_BLK;
    float* hout = out + OFF_H + (size_t)n * Dv + d;

    #pragma unroll 4
    for (int bl = 0; bl < B_PER_BLK; ++bl) {
        const int b = b0 + bl;
        const float zv = __ldg(z + b * Nv + n);              // broadcast within block
        hout[(size_t)b * (Nv * Dv)] = fast_tanh(fmaf(zv, a, c));
    }
}

// Edge streams: one thread = 4 consecutive flat edge ids (same b, same r).
//   i = b*N*N + r*N + c ; j = i mod N*N
//   row[i]=b*N+r  col[i]=b*N+c  wgt[i]=adj[j]  typ[i]=j+1
__global__ void __launch_bounds__(256) edges_kernel(
    const float* __restrict__ adj,
    float* __restrict__ out)
{
    const int g = blockIdx.x * blockDim.x + threadIdx.x;     // float4 group id
    const int i = g << 2;
    const int b = i >> 14;            // / 16384
    const int j = i & 16383;          // mod N*N
    const int r = j >> 7;
    const int c = j & 127;

    const float4 w4 = *reinterpret_cast<const float4*>(adj + j);

    const float rowv = (float)(b * Nv + r);
    const float4 row4 = make_float4(rowv, rowv, rowv, rowv);

    const float colb = (float)(b * Nv + c);
    const float4 col4 = make_float4(colb, colb + 1.0f, colb + 2.0f, colb + 3.0f);

    const float tb = (float)(j + 1);
    const float4 t4 = make_float4(tb, tb + 1.0f, tb + 2.0f, tb + 3.0f);

    reinterpret_cast<float4*>(out + OFF_ROW)[g] = row4;
    reinterpret_cast<float4*>(out + OFF_COL)[g] = col4;
    reinterpret_cast<float4*>(out + OFF_W  )[g] = w4;
    reinterpret_cast<float4*>(out + OFF_T  )[g] = t4;
}

// Safety fallback: identical math, every store bounds-checked against the real
// out_size. Only used if out_size != TOTAL_OUT (layout assumption wrong) so a
// mismatch yields a clean rel_err diagnostic instead of an OOB crash.
__global__ void __launch_bounds__(256) fallback_kernel(
    const float* __restrict__ z,
    const float* __restrict__ adj,
    const float* __restrict__ W,
    const float* __restrict__ bias,
    float* __restrict__ out, int out_n)
{
    for (long long idx = blockIdx.x * 256LL + threadIdx.x;
         idx < (long long)TOTAL_OUT;
         idx += (long long)gridDim.x * 256LL)
    {
        float v;
        if (idx < OFF_ROW) {                       // h
            int t = (int)idx;
            int d = t & (Dv - 1);  t >>= 8;
            int n = t & (Nv - 1);  t >>= 7;
            int b = t;
            const float* Wn = W + (size_t)n * (Fv * Dv);
            float a = Wn[d];
            float c = Wn[(n + 1) * Dv + d] + bias[n * Dv + d];
            v = fast_tanh(fmaf(z[b * Nv + n], a, c));
        } else if (idx < OFF_COL) {                // row
            int i = (int)(idx - OFF_ROW);
            v = (float)((i >> 14) * Nv + ((i & 16383) >> 7));
        } else if (idx < OFF_W) {                  // col
            int i = (int)(idx - OFF_COL);
            v = (float)((i >> 14) * Nv + (i & 127));
        } else if (idx < OFF_T) {                  // weights
            int i = (int)(idx - OFF_W);
            v = adj[i & 16383];
        } else {                                   // types
            int i = (int)(idx - OFF_T);
            v = (float)((i & 16383) + 1);
        }
        if (idx < out_n) out[idx] = v;
    }
}

extern "C" void kernel_launch(void* const* d_in, const int* in_sizes, int n_in,
                              void* d_out, int out_size)
{
    const float* z    = (const float*)d_in[0];   // [B, N]
    const float* adj  = (const float*)d_in[1];   // [N, N]
    const float* W    = (const float*)d_in[2];   // [N, F, D]
    const float* bias = (const float*)d_in[3];   // [N, D]
    float* out = (float*)d_out;

    if (out_size == TOTAL_OUT) {
        dim3 hgrid(Nv, Bv / B_PER_BLK);
        h_kernel<<<hgrid, Dv>>>(z, W, bias, out);

        const int groups = (Bv * Nv * Nv) / 4;   // 2,097,152
        edges_kernel<<<groups / 256, 256>>>(adj, out);
    } else {
        // Layout assumption violated — run the bounds-checked fallback so we
        // get a rel_err diagnostic instead of a crash.
        fallback_kernel<<<2048, 256>>>(z, adj, W, bias, out, out_size);
    }
}

// round 4
// speedup vs baseline: 1.1769x; 1.1769x over previous
#include <cuda_runtime.h>
#include <stdint.h>

// Problem constants (fixed by reference setup_inputs)
#define Bv 512
#define Nv 128
#define Dv 256
#define Fv (Nv + 1)          // 129

// Output layout (concatenated flattened reference outputs, float32):
#define OFF_H    0
#define OFF_ROW  (Bv*Nv*Dv)                       // 16777216
#define OFF_COL  (OFF_ROW + Bv*Nv*Nv)             // 25165824
#define OFF_W    (OFF_COL + Bv*Nv*Nv)             // 33554432
#define OFF_T    (OFF_W   + Bv*Nv*Nv)             // 41943040
#define TOTAL_OUT (OFF_T + Bv*Nv*Nv)              // 50331648

#define EDGE_BLOCKS 8192          // 8192 * 256 threads * 4 edges = 8,388,608 edges
#define H_BLOCKS    2048          // 128 nodes * 16 batch-chunks
#define ALL_BLOCKS  (EDGE_BLOCKS + H_BLOCKS)      // 10240 = 5 * 2048

__device__ __forceinline__ float fast_tanh(float x) {
    float y;
    asm("tanh.approx.f32 %0, %1;" : "=f"(y) : "f"(x));
    return y;
}

__device__ __forceinline__ void stcs4(float* p, float4 v) {
    __stcs(reinterpret_cast<float4*>(p), v);
}

// Fused kernel. Block roles striped 1:4 (h:edges) so both store mixes coexist
// in every wave and DRAM stays saturated end-to-end.
//
// h role:    h[b,n,d] = tanh( z[b,n]*W[n,0,d] + W[n,n+1,d] + bias[n,d] )
//            (one-hot in feats selects W row n+1; einsum degenerates to axpy)
//            block = 64 d-groups x 4 b-lanes; 8 iters; float4 stores.
// edge role: i = b*N*N + r*N + c ; j = i mod N*N
//            row[i]=b*N+r  col[i]=b*N+c  wgt[i]=adj[j]  typ[i]=j+1
//            thread = 4 consecutive edges -> 4 x STG.128.
__global__ void __launch_bounds__(256) fused_kernel(
    const float* __restrict__ z,
    const float* __restrict__ adj,
    const float* __restrict__ W,
    const float* __restrict__ bias,
    float* __restrict__ out)
{
    const int bid = blockIdx.x;
    const int tid = threadIdx.x;

    if ((bid % 5) == 0) {
        // ---- h role: hb in [0, 2048) ----
        const int hb = bid / 5;
        const int n  = hb & (Nv - 1);
        const int bc = hb >> 7;                   // batch chunk (32 batches)

        const int dg = tid & 63;                  // d-group: d = dg*4
        const int bl = tid >> 6;                  // 0..3

        const float4* Wn = reinterpret_cast<const float4*>(W + (size_t)n * (Fv * Dv));
        const float4 a4 = __ldg(Wn + dg);                        // W[n,0,d..d+3]
        float4 c4 = __ldg(Wn + (n + 1) * (Dv / 4) + dg);         // W[n,n+1,d..d+3]
        const float4 b4 = __ldg(reinterpret_cast<const float4*>(bias + n * Dv) + dg);
        c4.x += b4.x; c4.y += b4.y; c4.z += b4.z; c4.w += b4.w;

        float* hout = out + OFF_H + (size_t)n * Dv + dg * 4;

        #pragma unroll
        for (int it = 0; it < 8; ++it) {
            const int b = bc * 32 + it * 4 + bl;
            const float zv = __ldg(z + b * Nv + n);              // L1/L2 hit
            float4 y;
            y.x = fast_tanh(fmaf(zv, a4.x, c4.x));
            y.y = fast_tanh(fmaf(zv, a4.y, c4.y));
            y.z = fast_tanh(fmaf(zv, a4.z, c4.z));
            y.w = fast_tanh(fmaf(zv, a4.w, c4.w));
            stcs4(hout + (size_t)b * (Nv * Dv), y);
        }
    } else {
        // ---- edge role: eb in [0, 8192) ----
        const int eb = bid - (bid / 5) - 1;
        const int g  = eb * 256 + tid;            // float4 group id
        const int i  = g << 2;
        const int b  = i >> 14;                   // / (N*N)
        const int j  = i & 16383;                 // mod N*N
        const int r  = j >> 7;
        const int c  = j & 127;

        const float4 w4 = __ldg(reinterpret_cast<const float4*>(adj + j));

        const float rowv = (float)(b * Nv + r);
        const float4 row4 = make_float4(rowv, rowv, rowv, rowv);

        const float colb = (float)(b * Nv + c);
        const float4 col4 = make_float4(colb, colb + 1.0f, colb + 2.0f, colb + 3.0f);

        const float tb = (float)(j + 1);
        const float4 t4 = make_float4(tb, tb + 1.0f, tb + 2.0f, tb + 3.0f);

        stcs4(out + OFF_ROW + (size_t)i, row4);
        stcs4(out + OFF_COL + (size_t)i, col4);
        stcs4(out + OFF_W   + (size_t)i, w4);
        stcs4(out + OFF_T   + (size_t)i, t4);
    }
}

// Safety fallback: identical math, bounds-checked stores (used only if the
// out_size/layout assumption were violated).
__global__ void __launch_bounds__(256) fallback_kernel(
    const float* __restrict__ z,
    const float* __restrict__ adj,
    const float* __restrict__ W,
    const float* __restrict__ bias,
    float* __restrict__ out, int out_n)
{
    for (long long idx = blockIdx.x * 256LL + threadIdx.x;
         idx < (long long)TOTAL_OUT;
         idx += (long long)gridDim.x * 256LL)
    {
        float v;
        if (idx < OFF_ROW) {
            int t = (int)idx;
            int d = t & (Dv - 1);  t >>= 8;
            int n = t & (Nv - 1);  t >>= 7;
            int b = t;
            const float* Wn = W + (size_t)n * (Fv * Dv);
            float a = Wn[d];
            float c = Wn[(n + 1) * Dv + d] + bias[n * Dv + d];
            v = fast_tanh(fmaf(z[b * Nv + n], a, c));
        } else if (idx < OFF_W) {
            int i = (int)(idx - OFF_ROW);
            int k = i & (Bv*Nv*Nv - 1);
            if (idx < OFF_COL) v = (float)((k >> 14) * Nv + ((k & 16383) >> 7));
            else               v = (float)((k >> 14) * Nv + (k & 127));
        } else if (idx < OFF_T) {
            int i = (int)(idx - OFF_W);
            v = adj[i & 16383];
        } else {
            int i = (int)(idx - OFF_T);
            v = (float)((i & 16383) + 1);
        }
        if (idx < out_n) out[idx] = v;
    }
}

extern "C" void kernel_launch(void* const* d_in, const int* in_sizes, int n_in,
                              void* d_out, int out_size)
{
    const float* z    = (const float*)d_in[0];   // [B, N]
    const float* adj  = (const float*)d_in[1];   // [N, N]
    const float* W    = (const float*)d_in[2];   // [N, F, D]
    const float* bias = (const float*)d_in[3];   // [N, D]
    float* out = (float*)d_out;

    if (out_size == TOTAL_OUT) {
        fused_kernel<<<ALL_BLOCKS, 256>>>(z, adj, W, bias, out);
    } else {
        fallback_kernel<<<2048, 256>>>(z, adj, W, bias, out, out_size);
    }
}